// round 1
// baseline (speedup 1.0000x reference)
#include <cuda_runtime.h>
#include <math.h>

#define DIM 1024
#define BB 4
#define SS 2048
#define NH 16
#define HD 64
#define MROWS (BB*SS)   // 8192

// Scratch (device globals; no allocation allowed)
__device__ float g_Q[BB*NH*SS*HD];   // [b,h,s,d]
__device__ float g_K[BB*NH*SS*HD];
__device__ float g_V[BB*NH*SS*HD];
__device__ float g_Z[MROWS*DIM];     // [b*s, dim]

// ---------------------------------------------------------------------------
// GEMM: C = scale * (A[M,K] @ W^T), W row-major [N,K] (torch Linear weight).
// LAYOUT 0: write head layout  out[((b*NH+h)*SS+s)*HD+d]
// LAYOUT 1: plain row-major    out[r*DIM+c]
// Tiles: BM=BN=64, BK=16, 256 threads, 4x4 microtile per thread.
// ---------------------------------------------------------------------------
template<int LAYOUT>
__global__ __launch_bounds__(256)
void gemm_xwt(const float* __restrict__ A, const float* __restrict__ W,
              float* __restrict__ C, float scale)
{
    __shared__ float As[16][68];   // [k][m]
    __shared__ float Bs[16][68];   // [k][n]
    const int tid  = threadIdx.x;
    const int row0 = blockIdx.x * 64;
    const int col0 = blockIdx.y * 64;
    const int tx = tid & 15, ty = tid >> 4;
    const int lr = tid >> 2;            // 0..63
    const int lc = (tid & 3) << 2;      // 0,4,8,12

    float acc[4][4] = {};
    const float* Aptr = A + (size_t)(row0 + lr) * DIM + lc;
    const float* Wptr = W + (size_t)(col0 + lr) * DIM + lc;

    for (int kt = 0; kt < DIM; kt += 16) {
        float4 a = *(const float4*)(Aptr + kt);
        float4 b = *(const float4*)(Wptr + kt);
        As[lc+0][lr] = a.x; As[lc+1][lr] = a.y; As[lc+2][lr] = a.z; As[lc+3][lr] = a.w;
        Bs[lc+0][lr] = b.x; Bs[lc+1][lr] = b.y; Bs[lc+2][lr] = b.z; Bs[lc+3][lr] = b.w;
        __syncthreads();
#pragma unroll
        for (int k = 0; k < 16; k++) {
            float4 ra = *(const float4*)&As[k][ty*4];
            float4 rb = *(const float4*)&Bs[k][tx*4];
            float am[4] = {ra.x, ra.y, ra.z, ra.w};
            float bn[4] = {rb.x, rb.y, rb.z, rb.w};
#pragma unroll
            for (int i = 0; i < 4; i++)
#pragma unroll
                for (int j = 0; j < 4; j++)
                    acc[i][j] = fmaf(am[i], bn[j], acc[i][j]);
        }
        __syncthreads();
    }

#pragma unroll
    for (int i = 0; i < 4; i++) {
        int r = row0 + ty*4 + i;
#pragma unroll
        for (int j = 0; j < 4; j++) {
            int c = col0 + tx*4 + j;
            float v = acc[i][j] * scale;
            if (LAYOUT == 0) {
                int b = r / SS, s = r % SS;
                int h = c / HD, d = c % HD;
                C[(size_t)((b*NH + h)*SS + s)*HD + d] = v;
            } else {
                C[(size_t)r*DIM + c] = v;
            }
        }
    }
}

// ---------------------------------------------------------------------------
// Flash-style attention: one CTA handles 64 q-rows of one (b,h).
// Online softmax; P staged through smem for the PV GEMM.
// Scale 1/sqrt(HD) is pre-folded into the Q projection.
// ---------------------------------------------------------------------------
__global__ __launch_bounds__(256)
void attn_kernel(const float* __restrict__ mask)
{
    extern __shared__ float smem[];
    float (*Qs)[68] = (float(*)[68])(smem);              // [d][q]
    float (*Ks)[68] = (float(*)[68])(smem + 64*68);      // [d][k]
    float (*Vs)[68] = (float(*)[68])(smem + 2*64*68);    // [k][d]
    float (*Ps)[68] = (float(*)[68])(smem + 3*64*68);    // [k][q]

    const int tid = threadIdx.x;
    const int tx = tid & 15, ty = tid >> 4;
    const int q0 = blockIdx.x * 64;
    const int bh = blockIdx.y;           // b*NH + h
    const int b  = bh / NH;
    const int h  = bh % NH;
    const int lr = tid >> 2;             // 0..63
    const int lc = (tid & 3) << 2;       // 0,4,8,12

    // Load Q tile transposed -> Qs[d][q]
    const float* Qg = g_Q + (size_t)(bh*SS + q0) * HD;
#pragma unroll
    for (int c = 0; c < 4; c++) {
        int d = lc + 16*c;
        float4 a = *(const float4*)(Qg + (size_t)lr*HD + d);
        Qs[d+0][lr] = a.x; Qs[d+1][lr] = a.y; Qs[d+2][lr] = a.z; Qs[d+3][lr] = a.w;
    }

    float m[4], l[4], o[4][4];
#pragma unroll
    for (int i = 0; i < 4; i++) {
        m[i] = -INFINITY; l[i] = 0.f;
#pragma unroll
        for (int j = 0; j < 4; j++) o[i][j] = 0.f;
    }

    for (int kt = 0; kt < SS; kt += 64) {
        const float* Kg = g_K + (size_t)(bh*SS + kt) * HD;
        const float* Vg = g_V + (size_t)(bh*SS + kt) * HD;
        __syncthreads();   // previous iter's smem reads done (also covers Q load, iter 0)
#pragma unroll
        for (int c = 0; c < 4; c++) {
            int d = lc + 16*c;
            float4 a = *(const float4*)(Kg + (size_t)lr*HD + d);
            Ks[d+0][lr] = a.x; Ks[d+1][lr] = a.y; Ks[d+2][lr] = a.z; Ks[d+3][lr] = a.w;
            float4 v = *(const float4*)(Vg + (size_t)lr*HD + d);
            *(float4*)&Vs[lr][d] = v;
        }
        __syncthreads();

        // Score tile S[q][k] = sum_d Qs[d][q] * Ks[d][k]
        float s[4][4] = {};
#pragma unroll
        for (int d = 0; d < HD; d++) {
            float4 ra = *(const float4*)&Qs[d][ty*4];
            float4 rb = *(const float4*)&Ks[d][tx*4];
            float am[4] = {ra.x, ra.y, ra.z, ra.w};
            float bn[4] = {rb.x, rb.y, rb.z, rb.w};
#pragma unroll
            for (int i = 0; i < 4; i++)
#pragma unroll
                for (int j = 0; j < 4; j++)
                    s[i][j] = fmaf(am[i], bn[j], s[i][j]);
        }

        // mask[b][0][q][k]
        const float* Mg = mask + ((size_t)b*SS + q0)*SS + kt;
#pragma unroll
        for (int i = 0; i < 4; i++) {
            int q = ty*4 + i;
#pragma unroll
            for (int j = 0; j < 4; j++)
                s[i][j] += Mg[(size_t)q*SS + tx*4 + j];
        }

        // Online softmax (row reduce across the 16 tx-lanes)
#pragma unroll
        for (int i = 0; i < 4; i++) {
            float tm = fmaxf(fmaxf(s[i][0], s[i][1]), fmaxf(s[i][2], s[i][3]));
#pragma unroll
            for (int off = 1; off < 16; off <<= 1)
                tm = fmaxf(tm, __shfl_xor_sync(0xffffffffu, tm, off, 16));
            float mn = fmaxf(m[i], tm);
            float corr = __expf(m[i] - mn);
            m[i] = mn;
            float ts = 0.f;
#pragma unroll
            for (int j = 0; j < 4; j++) { s[i][j] = __expf(s[i][j] - mn); ts += s[i][j]; }
#pragma unroll
            for (int off = 1; off < 16; off <<= 1)
                ts += __shfl_xor_sync(0xffffffffu, ts, off, 16);
            l[i] = l[i]*corr + ts;
#pragma unroll
            for (int j = 0; j < 4; j++) o[i][j] *= corr;
        }

        // Stage P transposed: Ps[k][q]
#pragma unroll
        for (int i = 0; i < 4; i++)
#pragma unroll
            for (int j = 0; j < 4; j++)
                Ps[tx*4 + j][ty*4 + i] = s[i][j];
        __syncthreads();

        // O[q][d] += sum_k Ps[k][q] * Vs[k][d]
#pragma unroll
        for (int k = 0; k < 64; k++) {
            float4 ra = *(const float4*)&Ps[k][ty*4];
            float4 rb = *(const float4*)&Vs[k][tx*4];
            float am[4] = {ra.x, ra.y, ra.z, ra.w};
            float bn[4] = {rb.x, rb.y, rb.z, rb.w};
#pragma unroll
            for (int i = 0; i < 4; i++)
#pragma unroll
                for (int j = 0; j < 4; j++)
                    o[i][j] = fmaf(am[i], bn[j], o[i][j]);
        }
    }

    // Epilogue: normalize, write Z[b*SS+q][h*HD+d]
#pragma unroll
    for (int i = 0; i < 4; i++) {
        int q = q0 + ty*4 + i;
        float inv = 1.f / l[i];
#pragma unroll
        for (int j = 0; j < 4; j++)
            g_Z[(size_t)(b*SS + q)*DIM + h*HD + tx*4 + j] = o[i][j] * inv;
    }
}

// ---------------------------------------------------------------------------
extern "C" void kernel_launch(void* const* d_in, const int* in_sizes, int n_in,
                              void* d_out, int out_size)
{
    const float* q    = (const float*)d_in[0];
    const float* k    = (const float*)d_in[1];
    const float* v    = (const float*)d_in[2];
    const float* mask = (const float*)d_in[3];
    const float* Wq   = (const float*)d_in[4];
    const float* Wk   = (const float*)d_in[5];
    const float* Wv   = (const float*)d_in[6];
    const float* Wd   = (const float*)d_in[7];
    // d_in[8] = time_lengths (unused by reference)

    float *gq, *gk, *gv, *gz;
    cudaGetSymbolAddress((void**)&gq, g_Q);
    cudaGetSymbolAddress((void**)&gk, g_K);
    cudaGetSymbolAddress((void**)&gv, g_V);
    cudaGetSymbolAddress((void**)&gz, g_Z);

    const int ATTN_SMEM = 4 * 64 * 68 * sizeof(float);   // 69632 B
    cudaFuncSetAttribute(attn_kernel, cudaFuncAttributeMaxDynamicSharedMemorySize, ATTN_SMEM);

    dim3 gp(MROWS/64, DIM/64);   // 128 x 16
    gemm_xwt<0><<<gp, 256>>>(q, Wq, gq, 0.125f);  // fold 1/sqrt(64) into Q
    gemm_xwt<0><<<gp, 256>>>(k, Wk, gk, 1.0f);
    gemm_xwt<0><<<gp, 256>>>(v, Wv, gv, 1.0f);

    attn_kernel<<<dim3(SS/64, BB*NH), 256, ATTN_SMEM>>>(mask);

    gemm_xwt<1><<<gp, 256>>>(gz, Wd, (float*)d_out, 1.0f);
}

// round 3
// speedup vs baseline: 3.4433x; 3.4433x over previous
#include <cuda_runtime.h>
#include <math.h>
#include <stdint.h>

#define DIM 1024
#define BB 4
#define SS 2048
#define NH 16
#define HD 64
#define MROWS (BB*SS)   // 8192

// ---------------------------------------------------------------------------
// Scratch (device globals; no allocation allowed)
// ---------------------------------------------------------------------------
__device__ float g_Q[BB*NH*SS*HD];   // [b,h,s,d] projected Q (x 1/8), tf32-rounded
__device__ float g_K[BB*NH*SS*HD];   // tf32-rounded
__device__ float g_V[BB*NH*SS*HD];   // tf32-rounded
__device__ float g_Z[MROWS*DIM];     // attention out, tf32-rounded
__device__ float g_RQ[MROWS*DIM];
__device__ float g_RK[MROWS*DIM];
__device__ float g_RV[MROWS*DIM];
__device__ float g_RW[4][DIM*DIM];
__device__ int   g_maskflag;

// ---------------------------------------------------------------------------
// Helpers (all compute_103-legal: sm_80-era PTX only)
// ---------------------------------------------------------------------------
__device__ __forceinline__ uint32_t smem_u32(const void* p) {
    uint32_t a;
    asm("{ .reg .u64 t; cvta.to.shared.u64 t, %1; cvt.u32.u64 %0, t; }" : "=r"(a) : "l"(p));
    return a;
}
__device__ __forceinline__ void cp16(uint32_t dst, const void* src) {
    asm volatile("cp.async.cg.shared.global [%0], [%1], 16;" :: "r"(dst), "l"(src));
}
#define CP_COMMIT() asm volatile("cp.async.commit_group;" ::: "memory")

__device__ __forceinline__ float rna_tf32(float x) {
    uint32_t r;
    asm("cvt.rna.tf32.f32 %0, %1;" : "=r"(r) : "f"(x));
    return __uint_as_float(r);
}

// D += A*B, m16n8k8 tf32 (HMMA path on sm_103)
__device__ __forceinline__ void mma_tf32(float d[4], const uint32_t a[4], const uint32_t b[2]) {
    asm volatile(
        "mma.sync.aligned.m16n8k8.row.col.f32.tf32.tf32.f32 "
        "{%0,%1,%2,%3}, {%4,%5,%6,%7}, {%8,%9}, {%0,%1,%2,%3};"
        : "+f"(d[0]), "+f"(d[1]), "+f"(d[2]), "+f"(d[3])
        : "r"(a[0]), "r"(a[1]), "r"(a[2]), "r"(a[3]), "r"(b[0]), "r"(b[1]));
}

// ---------------------------------------------------------------------------
// tf32 round-to-nearest pre-pass
// ---------------------------------------------------------------------------
__global__ __launch_bounds__(256)
void round_tf32(const float* __restrict__ in, float* __restrict__ out) {
    int i = (blockIdx.x * 256 + threadIdx.x) * 4;
    float4 v = *(const float4*)(in + i);
    v.x = rna_tf32(v.x); v.y = rna_tf32(v.y); v.z = rna_tf32(v.z); v.w = rna_tf32(v.w);
    *(float4*)(out + i) = v;
}

// mask-nonzero scan
__global__ __launch_bounds__(256)
void reset_flag() { g_maskflag = 0; }
__global__ __launch_bounds__(256)
void scan_mask(const float* __restrict__ m) {
    int i = (blockIdx.x * 256 + threadIdx.x) * 4;
    float4 v = *(const float4*)(m + i);
    if (v.x != 0.f || v.y != 0.f || v.z != 0.f || v.w != 0.f)
        atomicExch(&g_maskflag, 1);
}

// ---------------------------------------------------------------------------
// mma.sync tf32 GEMM: C[M,N] = scale * (A[M,K] @ W[N,K]^T), K=1024.
// BM=BN=128, BK=16, 256 threads (8 warps, 4x2), 4-stage cp.async pipeline.
// LAYOUT 0: head layout  out[((b*NH+h)*SS+s)*HD+d];  LAYOUT 1: row-major.
// ROUND 1: tf32-round outputs.
// ---------------------------------------------------------------------------
#define PST 20                       // smem row stride (16 + 4 pad), floats
#define STG_F (2 * 128 * PST)        // A+B floats per stage = 5120
#define GEMM_SMEM (4 * STG_F * 4)    // 81920 bytes

template<int LAYOUT, int ROUND>
__global__ __launch_bounds__(256)
void gemm_mma(const float* __restrict__ A, const float* __restrict__ W,
              float* __restrict__ C, float scale)
{
    extern __shared__ float sm[];
    const int tid = threadIdx.x;
    const int lane = tid & 31, wid = tid >> 5;
    const int wr = wid >> 1, wc = wid & 1;       // 4x2 warp grid
    const int r0 = lane >> 2, c0 = lane & 3;
    const int row0 = blockIdx.x * 128, col0 = blockIdx.y * 128;
    const uint32_t smb = smem_u32(sm);

    float acc[2][8][4];
#pragma unroll
    for (int mt = 0; mt < 2; mt++)
#pragma unroll
        for (int nt = 0; nt < 8; nt++)
#pragma unroll
            for (int j = 0; j < 4; j++) acc[mt][nt][j] = 0.f;

    auto load_stage = [&](int kt, int s) {
        uint32_t a_s = smb + s * (STG_F * 4);
        uint32_t b_s = a_s + 128 * PST * 4;
#pragma unroll
        for (int i = 0; i < 2; i++) {
            int c = tid + 256 * i;               // 0..511
            int row = c >> 2, c4 = c & 3;
            uint32_t so = (uint32_t)(row * PST + c4 * 4) * 4;
            cp16(a_s + so, A + (size_t)(row0 + row) * DIM + kt * 16 + c4 * 4);
            cp16(b_s + so, W + (size_t)(col0 + row) * DIM + kt * 16 + c4 * 4);
        }
    };

    load_stage(0, 0); CP_COMMIT();
    load_stage(1, 1); CP_COMMIT();
    load_stage(2, 2); CP_COMMIT();

    const int NT = DIM / 16;                     // 64
    for (int kt = 0; kt < NT; kt++) {
        asm volatile("cp.async.wait_group 2;" ::: "memory");
        __syncthreads();                         // stage kt ready; prev compute done
        if (kt + 3 < NT) load_stage(kt + 3, (kt + 3) & 3);
        CP_COMMIT();

        const float* As = sm + (kt & 3) * STG_F;
        const float* Bs = As + 128 * PST;
#pragma unroll
        for (int ks = 0; ks < 2; ks++) {
            const int kb = ks * 8;
            uint32_t a[2][4];
#pragma unroll
            for (int mt = 0; mt < 2; mt++) {
                const int R = wr * 32 + mt * 16;
                a[mt][0] = __float_as_uint(As[(R + r0)     * PST + kb + c0]);
                a[mt][1] = __float_as_uint(As[(R + r0 + 8) * PST + kb + c0]);
                a[mt][2] = __float_as_uint(As[(R + r0)     * PST + kb + c0 + 4]);
                a[mt][3] = __float_as_uint(As[(R + r0 + 8) * PST + kb + c0 + 4]);
            }
#pragma unroll
            for (int nt = 0; nt < 8; nt++) {
                const int Nb = wc * 64 + nt * 8;
                uint32_t b[2];
                b[0] = __float_as_uint(Bs[(Nb + r0) * PST + kb + c0]);
                b[1] = __float_as_uint(Bs[(Nb + r0) * PST + kb + c0 + 4]);
                mma_tf32(acc[0][nt], a[0], b);
                mma_tf32(acc[1][nt], a[1], b);
            }
        }
    }

    // epilogue
    const int h = (col0 + wc * 64) >> 6;         // head index (LAYOUT 0)
#pragma unroll
    for (int mt = 0; mt < 2; mt++) {
        const int rA = row0 + wr * 32 + mt * 16 + r0;
#pragma unroll
        for (int rr = 0; rr < 2; rr++) {
            const int r = rA + rr * 8;
#pragma unroll
            for (int nt = 0; nt < 8; nt++) {
                const int d = nt * 8 + 2 * c0;   // 0..63 within warp col block
                float v0 = acc[mt][nt][rr * 2 + 0] * scale;
                float v1 = acc[mt][nt][rr * 2 + 1] * scale;
                if (ROUND) { v0 = rna_tf32(v0); v1 = rna_tf32(v1); }
                float2 val = make_float2(v0, v1);
                if (LAYOUT == 0) {
                    const int b = r >> 11, s = r & (SS - 1);
                    *(float2*)(C + ((size_t)((b * NH + h) * SS) + s) * HD + d) = val;
                } else {
                    *(float2*)(C + (size_t)r * DIM + col0 + wc * 64 + d) = val;
                }
            }
        }
    }
}

// ---------------------------------------------------------------------------
// mma.sync tf32 flash attention.
// CTA: 256 thr (8 warps), 128 q-rows (16/warp), loop over 32 k-blocks of 64.
// Ks [64][68], Vs [64][72], Ps [128][68] (per-warp P tiles; also Q staging).
// ---------------------------------------------------------------------------
#define KST 68
#define VST 72
#define ATTN_SMEM ((64*KST + 64*VST + 128*KST) * 4)   // 70656 B

__global__ __launch_bounds__(256, 2)
void attn_mma(const float* __restrict__ mask)
{
    extern __shared__ float sm[];
    float* Ks = sm;                    // [64][68]
    float* Vs = sm + 64 * KST;         // [64][72]
    float* Ps = sm + 64 * KST + 64 * VST;  // [128][68]

    const int tid = threadIdx.x, lane = tid & 31, w = tid >> 5;
    const int r0 = lane >> 2, c0 = lane & 3;
    const int q0 = blockIdx.x * 128;
    const int bh = blockIdx.y, b = bh >> 4, h = bh & 15;
    const int use_mask = g_maskflag;

    // stage Q tile into Ps, then pull fragments
    const float* Qg = g_Q + ((size_t)bh * SS + q0) * HD;
#pragma unroll
    for (int i = 0; i < 8; i++) {
        int c = tid + 256 * i;                 // 0..2047
        int row = c >> 4, c4 = c & 15;
        *(float4*)&Ps[row * KST + c4 * 4] = *(const float4*)(Qg + (size_t)row * HD + c4 * 4);
    }
    __syncthreads();
    uint32_t qf[8][4];
#pragma unroll
    for (int ks = 0; ks < 8; ks++) {
        const float* Qr = &Ps[(w * 16 + r0) * KST + ks * 8 + c0];
        qf[ks][0] = __float_as_uint(Qr[0]);
        qf[ks][1] = __float_as_uint(Qr[8 * KST]);
        qf[ks][2] = __float_as_uint(Qr[4]);
        qf[ks][3] = __float_as_uint(Qr[8 * KST + 4]);
    }
    __syncthreads();

    float o[8][4];
#pragma unroll
    for (int nt = 0; nt < 8; nt++)
#pragma unroll
        for (int j = 0; j < 4; j++) o[nt][j] = 0.f;
    float m_lo = -INFINITY, m_hi = -INFINITY, l_lo = 0.f, l_hi = 0.f;

    const float* Kg0 = g_K + (size_t)bh * SS * HD;
    const float* Vg0 = g_V + (size_t)bh * SS * HD;

    for (int kt = 0; kt < SS; kt += 64) {
        __syncthreads();
#pragma unroll
        for (int i = 0; i < 4; i++) {
            int c = tid + 256 * i;             // 0..1023
            int row = c >> 4, c4 = c & 15;
            *(float4*)&Ks[row * KST + c4 * 4] =
                *(const float4*)(Kg0 + (size_t)(kt + row) * HD + c4 * 4);
            *(float4*)&Vs[row * VST + c4 * 4] =
                *(const float4*)(Vg0 + (size_t)(kt + row) * HD + c4 * 4);
        }
        __syncthreads();

        // S = Q @ K^T  (per warp: 16 x 64)
        float s[8][4];
#pragma unroll
        for (int nt = 0; nt < 8; nt++) {
#pragma unroll
            for (int j = 0; j < 4; j++) s[nt][j] = 0.f;
#pragma unroll
            for (int ks = 0; ks < 8; ks++) {
                const float* Kr = &Ks[(nt * 8 + r0) * KST + ks * 8 + c0];
                uint32_t bb[2];
                bb[0] = __float_as_uint(Kr[0]);
                bb[1] = __float_as_uint(Kr[4]);
                mma_tf32(s[nt], qf[ks], bb);
            }
        }

        if (use_mask) {
            const float* Mg = mask + ((size_t)b * SS + (q0 + w * 16 + r0)) * SS + kt;
#pragma unroll
            for (int nt = 0; nt < 8; nt++) {
                float2 mlo = *(const float2*)(Mg + nt * 8 + 2 * c0);
                float2 mhi = *(const float2*)(Mg + (size_t)8 * SS + nt * 8 + 2 * c0);
                s[nt][0] += mlo.x; s[nt][1] += mlo.y;
                s[nt][2] += mhi.x; s[nt][3] += mhi.y;
            }
        }

        // online softmax (rows r0 -> lo, r0+8 -> hi; reduce across quad)
        float mx_lo = -INFINITY, mx_hi = -INFINITY;
#pragma unroll
        for (int nt = 0; nt < 8; nt++) {
            mx_lo = fmaxf(mx_lo, fmaxf(s[nt][0], s[nt][1]));
            mx_hi = fmaxf(mx_hi, fmaxf(s[nt][2], s[nt][3]));
        }
        mx_lo = fmaxf(mx_lo, __shfl_xor_sync(0xffffffffu, mx_lo, 1));
        mx_lo = fmaxf(mx_lo, __shfl_xor_sync(0xffffffffu, mx_lo, 2));
        mx_hi = fmaxf(mx_hi, __shfl_xor_sync(0xffffffffu, mx_hi, 1));
        mx_hi = fmaxf(mx_hi, __shfl_xor_sync(0xffffffffu, mx_hi, 2));
        const float nm_lo = fmaxf(m_lo, mx_lo), nm_hi = fmaxf(m_hi, mx_hi);
        const float corr_lo = __expf(m_lo - nm_lo), corr_hi = __expf(m_hi - nm_hi);
        m_lo = nm_lo; m_hi = nm_hi;

        float sum_lo = 0.f, sum_hi = 0.f;
        float* Pw0 = &Ps[(w * 16 + r0) * KST];
        float* Pw1 = Pw0 + 8 * KST;
#pragma unroll
        for (int nt = 0; nt < 8; nt++) {
            float p0 = __expf(s[nt][0] - nm_lo);
            float p1 = __expf(s[nt][1] - nm_lo);
            float p2 = __expf(s[nt][2] - nm_hi);
            float p3 = __expf(s[nt][3] - nm_hi);
            sum_lo += p0 + p1; sum_hi += p2 + p3;
            *(float2*)(Pw0 + nt * 8 + 2 * c0) = make_float2(rna_tf32(p0), rna_tf32(p1));
            *(float2*)(Pw1 + nt * 8 + 2 * c0) = make_float2(rna_tf32(p2), rna_tf32(p3));
        }
        sum_lo += __shfl_xor_sync(0xffffffffu, sum_lo, 1);
        sum_lo += __shfl_xor_sync(0xffffffffu, sum_lo, 2);
        sum_hi += __shfl_xor_sync(0xffffffffu, sum_hi, 1);
        sum_hi += __shfl_xor_sync(0xffffffffu, sum_hi, 2);
        l_lo = l_lo * corr_lo + sum_lo;
        l_hi = l_hi * corr_hi + sum_hi;
#pragma unroll
        for (int nt = 0; nt < 8; nt++) {
            o[nt][0] *= corr_lo; o[nt][1] *= corr_lo;
            o[nt][2] *= corr_hi; o[nt][3] *= corr_hi;
        }
        __syncwarp();

        // O += P @ V  (per warp: 16 x 64)
#pragma unroll
        for (int ks = 0; ks < 8; ks++) {
            const float* Pr = &Ps[(w * 16 + r0) * KST + ks * 8 + c0];
            uint32_t aa[4];
            aa[0] = __float_as_uint(Pr[0]);
            aa[1] = __float_as_uint(Pr[8 * KST]);
            aa[2] = __float_as_uint(Pr[4]);
            aa[3] = __float_as_uint(Pr[8 * KST + 4]);
#pragma unroll
            for (int nt = 0; nt < 8; nt++) {
                uint32_t bb[2];
                bb[0] = __float_as_uint(Vs[(ks * 8 + c0)     * VST + nt * 8 + r0]);
                bb[1] = __float_as_uint(Vs[(ks * 8 + c0 + 4) * VST + nt * 8 + r0]);
                mma_tf32(o[nt], aa, bb);
            }
        }
        __syncwarp();
    }

    // epilogue: normalize, round to tf32, write Z[b*SS+q][h*HD+d]
    const float inv_lo = 1.f / l_lo, inv_hi = 1.f / l_hi;
    const int qlo = q0 + w * 16 + r0;
    float* Zlo = g_Z + ((size_t)b * SS + qlo) * DIM + h * HD;
    float* Zhi = Zlo + (size_t)8 * DIM;
#pragma unroll
    for (int nt = 0; nt < 8; nt++) {
        const int d = nt * 8 + 2 * c0;
        *(float2*)(Zlo + d) = make_float2(rna_tf32(o[nt][0] * inv_lo),
                                          rna_tf32(o[nt][1] * inv_lo));
        *(float2*)(Zhi + d) = make_float2(rna_tf32(o[nt][2] * inv_hi),
                                          rna_tf32(o[nt][3] * inv_hi));
    }
}

// ---------------------------------------------------------------------------
extern "C" void kernel_launch(void* const* d_in, const int* in_sizes, int n_in,
                              void* d_out, int out_size)
{
    const float* q    = (const float*)d_in[0];
    const float* k    = (const float*)d_in[1];
    const float* v    = (const float*)d_in[2];
    const float* mask = (const float*)d_in[3];
    const float* Wq   = (const float*)d_in[4];
    const float* Wk   = (const float*)d_in[5];
    const float* Wv   = (const float*)d_in[6];
    const float* Wd   = (const float*)d_in[7];

    float *gq, *gk, *gv, *gz, *rq, *rk, *rv;
    float (*rw)[DIM*DIM];
    cudaGetSymbolAddress((void**)&gq, g_Q);
    cudaGetSymbolAddress((void**)&gk, g_K);
    cudaGetSymbolAddress((void**)&gv, g_V);
    cudaGetSymbolAddress((void**)&gz, g_Z);
    cudaGetSymbolAddress((void**)&rq, g_RQ);
    cudaGetSymbolAddress((void**)&rk, g_RK);
    cudaGetSymbolAddress((void**)&rv, g_RV);
    cudaGetSymbolAddress((void**)&rw, g_RW);

    cudaFuncSetAttribute(gemm_mma<0,1>, cudaFuncAttributeMaxDynamicSharedMemorySize, GEMM_SMEM);
    cudaFuncSetAttribute(gemm_mma<1,0>, cudaFuncAttributeMaxDynamicSharedMemorySize, GEMM_SMEM);
    cudaFuncSetAttribute(attn_mma, cudaFuncAttributeMaxDynamicSharedMemorySize, ATTN_SMEM);

    const int NELT = MROWS * DIM;          // 8388608
    const int NW   = DIM * DIM;            // 1048576
    const int NM   = BB * SS * SS;         // 16777216

    // mask-nonzero flag
    reset_flag<<<1, 1>>>();
    scan_mask<<<NM/1024, 256>>>(mask);

    // tf32 pre-rounding of GEMM inputs
    round_tf32<<<NELT/1024, 256>>>(q, rq);
    round_tf32<<<NELT/1024, 256>>>(k, rk);
    round_tf32<<<NELT/1024, 256>>>(v, rv);
    round_tf32<<<NW/1024, 256>>>(Wq, rw[0]);
    round_tf32<<<NW/1024, 256>>>(Wk, rw[1]);
    round_tf32<<<NW/1024, 256>>>(Wv, rw[2]);
    round_tf32<<<NW/1024, 256>>>(Wd, rw[3]);

    // projections (epilogue rounds outputs to tf32 for attention mma)
    dim3 gp(MROWS/128, DIM/128);           // 64 x 8
    gemm_mma<0,1><<<gp, 256, GEMM_SMEM>>>(rq, rw[0], gq, 0.125f);  // fold 1/sqrt(64)
    gemm_mma<0,1><<<gp, 256, GEMM_SMEM>>>(rk, rw[1], gk, 1.0f);
    gemm_mma<0,1><<<gp, 256, GEMM_SMEM>>>(rv, rw[2], gv, 1.0f);

    // flash attention (tf32 mma), writes tf32-rounded Z
    attn_mma<<<dim3(SS/128, BB*NH), 256, ATTN_SMEM>>>(mask);

    // output projection
    gemm_mma<1,0><<<gp, 256, GEMM_SMEM>>>(gz, rw[3], (float*)d_out, 1.0f);
}

// round 4
// speedup vs baseline: 3.7572x; 1.0912x over previous
#include <cuda_runtime.h>
#include <math.h>
#include <stdint.h>

#define DIM 1024
#define BB 4
#define SS 2048
#define NH 16
#define HD 64
#define MROWS (BB*SS)   // 8192

// ---------------------------------------------------------------------------
// Scratch (device globals; no allocation allowed)
// ---------------------------------------------------------------------------
__device__ float g_Q[BB*NH*SS*HD];   // [b,h,s,d] projected Q (x 1/8), tf32-rounded
__device__ float g_K[BB*NH*SS*HD];   // tf32-rounded
__device__ float g_V[BB*NH*SS*HD];   // tf32-rounded
__device__ float g_Z[MROWS*DIM];     // attention out, tf32-rounded
__device__ float g_RQ[MROWS*DIM];
__device__ float g_RK[MROWS*DIM];
__device__ float g_RV[MROWS*DIM];
__device__ float g_RW[4][DIM*DIM];
__device__ int   g_maskflag;

// ---------------------------------------------------------------------------
// Helpers (compute_103-legal, sm_80-era PTX only)
// ---------------------------------------------------------------------------
__device__ __forceinline__ uint32_t smem_u32(const void* p) {
    uint32_t a;
    asm("{ .reg .u64 t; cvta.to.shared.u64 t, %1; cvt.u32.u64 %0, t; }" : "=r"(a) : "l"(p));
    return a;
}
__device__ __forceinline__ void cp16(uint32_t dst, const void* src) {
    asm volatile("cp.async.cg.shared.global [%0], [%1], 16;" :: "r"(dst), "l"(src));
}
#define CP_COMMIT() asm volatile("cp.async.commit_group;" ::: "memory")

__device__ __forceinline__ float rna_tf32(float x) {
    uint32_t r;
    asm("cvt.rna.tf32.f32 %0, %1;" : "=r"(r) : "f"(x));
    return __uint_as_float(r);
}

__device__ __forceinline__ void mma_tf32(float d[4], const uint32_t a[4], const uint32_t b[2]) {
    asm volatile(
        "mma.sync.aligned.m16n8k8.row.col.f32.tf32.tf32.f32 "
        "{%0,%1,%2,%3}, {%4,%5,%6,%7}, {%8,%9}, {%0,%1,%2,%3};"
        : "+f"(d[0]), "+f"(d[1]), "+f"(d[2]), "+f"(d[3])
        : "r"(a[0]), "r"(a[1]), "r"(a[2]), "r"(a[3]), "r"(b[0]), "r"(b[1]));
}

// ---------------------------------------------------------------------------
// tf32 round-to-nearest pre-pass / mask scan
// ---------------------------------------------------------------------------
__global__ __launch_bounds__(256)
void round_tf32(const float* __restrict__ in, float* __restrict__ out) {
    int i = (blockIdx.x * 256 + threadIdx.x) * 4;
    float4 v = *(const float4*)(in + i);
    v.x = rna_tf32(v.x); v.y = rna_tf32(v.y); v.z = rna_tf32(v.z); v.w = rna_tf32(v.w);
    *(float4*)(out + i) = v;
}
__global__ __launch_bounds__(256)
void reset_flag() { g_maskflag = 0; }
__global__ __launch_bounds__(256)
void scan_mask(const float* __restrict__ m) {
    int i = (blockIdx.x * 256 + threadIdx.x) * 4;
    float4 v = *(const float4*)(m + i);
    if (v.x != 0.f || v.y != 0.f || v.z != 0.f || v.w != 0.f)
        atomicExch(&g_maskflag, 1);
}

// ---------------------------------------------------------------------------
// mma.sync tf32 GEMM: C[M,N] = scale * (A[M,K] @ W[N,K]^T), K=1024.
// BM=BN=128, BK=16, 128 threads (4 warps 2x2, warp tile 64x64), 4-stage pipe.
// LAYOUT 0: head layout  out[((b*NH+h)*SS+s)*HD+d];  LAYOUT 1: row-major.
// ---------------------------------------------------------------------------
#define PST 20                       // smem row stride (16 + 4 pad), floats
#define STG_F (2 * 128 * PST)        // A+B floats per stage = 5120
#define GEMM_SMEM (4 * STG_F * 4)    // 81920 bytes

template<int LAYOUT, int ROUND>
__global__ __launch_bounds__(128, 2)
void gemm_mma(const float* __restrict__ A, const float* __restrict__ W,
              float* __restrict__ C, float scale)
{
    extern __shared__ float sm[];
    const int tid = threadIdx.x;
    const int lane = tid & 31, wid = tid >> 5;
    const int wr = wid >> 1, wc = wid & 1;       // 2x2 warp grid, warp tile 64x64
    const int r0 = lane >> 2, c0 = lane & 3;
    const int row0 = blockIdx.x * 128, col0 = blockIdx.y * 128;
    const uint32_t smb = smem_u32(sm);

    float acc[4][8][4];
#pragma unroll
    for (int mt = 0; mt < 4; mt++)
#pragma unroll
        for (int nt = 0; nt < 8; nt++)
#pragma unroll
            for (int j = 0; j < 4; j++) acc[mt][nt][j] = 0.f;

    auto load_stage = [&](int kt, int s) {
        uint32_t a_s = smb + s * (STG_F * 4);
        uint32_t b_s = a_s + 128 * PST * 4;
#pragma unroll
        for (int i = 0; i < 4; i++) {
            int c = tid + 128 * i;               // 0..511
            int row = c >> 2, c4 = c & 3;
            uint32_t so = (uint32_t)(row * PST + c4 * 4) * 4;
            cp16(a_s + so, A + (size_t)(row0 + row) * DIM + kt * 16 + c4 * 4);
            cp16(b_s + so, W + (size_t)(col0 + row) * DIM + kt * 16 + c4 * 4);
        }
    };

    load_stage(0, 0); CP_COMMIT();
    load_stage(1, 1); CP_COMMIT();
    load_stage(2, 2); CP_COMMIT();

    const int NT = DIM / 16;                     // 64
    for (int kt = 0; kt < NT; kt++) {
        asm volatile("cp.async.wait_group 2;" ::: "memory");
        __syncthreads();
        if (kt + 3 < NT) load_stage(kt + 3, (kt + 3) & 3);
        CP_COMMIT();

        const float* As = sm + (kt & 3) * STG_F;
        const float* Bs = As + 128 * PST;
#pragma unroll
        for (int ks = 0; ks < 2; ks++) {
            const int kb = ks * 8;
            uint32_t a[4][4];
#pragma unroll
            for (int mt = 0; mt < 4; mt++) {
                const int R = wr * 64 + mt * 16;
                a[mt][0] = __float_as_uint(As[(R + r0)     * PST + kb + c0]);
                a[mt][1] = __float_as_uint(As[(R + r0 + 8) * PST + kb + c0]);
                a[mt][2] = __float_as_uint(As[(R + r0)     * PST + kb + c0 + 4]);
                a[mt][3] = __float_as_uint(As[(R + r0 + 8) * PST + kb + c0 + 4]);
            }
#pragma unroll
            for (int nt = 0; nt < 8; nt++) {
                const int Nb = wc * 64 + nt * 8;
                uint32_t b[2];
                b[0] = __float_as_uint(Bs[(Nb + r0) * PST + kb + c0]);
                b[1] = __float_as_uint(Bs[(Nb + r0) * PST + kb + c0 + 4]);
#pragma unroll
                for (int mt = 0; mt < 4; mt++)
                    mma_tf32(acc[mt][nt], a[mt], b);
            }
        }
    }

    const int h = (col0 + wc * 64) >> 6;
#pragma unroll
    for (int mt = 0; mt < 4; mt++) {
        const int rA = row0 + wr * 64 + mt * 16 + r0;
#pragma unroll
        for (int rr = 0; rr < 2; rr++) {
            const int r = rA + rr * 8;
#pragma unroll
            for (int nt = 0; nt < 8; nt++) {
                const int d = nt * 8 + 2 * c0;
                float v0 = acc[mt][nt][rr * 2 + 0] * scale;
                float v1 = acc[mt][nt][rr * 2 + 1] * scale;
                if (ROUND) { v0 = rna_tf32(v0); v1 = rna_tf32(v1); }
                float2 val = make_float2(v0, v1);
                if (LAYOUT == 0) {
                    const int b = r >> 11, s = r & (SS - 1);
                    *(float2*)(C + ((size_t)((b * NH + h) * SS) + s) * HD + d) = val;
                } else {
                    *(float2*)(C + (size_t)r * DIM + col0 + wc * 64 + d) = val;
                }
            }
        }
    }
}

// ---------------------------------------------------------------------------
// mma.sync tf32 flash attention.
// CTA: 128 thr (4 warps), 128 q-rows (32/warp, mt=2), 64 iters of 32 keys.
// K/V double-buffered via cp.async. P staged per-warp through smem.
// smem: Ks 2x[32][68], Vs 2x[32][72], Ps [128][68]  (also Q staging) = 70656B
// ---------------------------------------------------------------------------
#define KST 68
#define VST 72
#define KS_F (32 * KST)              // 2176 floats per K stage
#define VS_F (32 * VST)              // 2304 floats per V stage
#define ATTN_SMEM ((2*KS_F + 2*VS_F + 128*KST) * 4)   // 70656 B

__global__ __launch_bounds__(128, 2)
void attn_mma(const float* __restrict__ mask)
{
    extern __shared__ float sm[];
    float* Ks = sm;                          // 2 stages
    float* Vs = sm + 2 * KS_F;               // 2 stages
    float* Ps = sm + 2 * KS_F + 2 * VS_F;    // [128][68]
    const uint32_t ks_b = smem_u32(Ks);
    const uint32_t vs_b = smem_u32(Vs);

    const int tid = threadIdx.x, lane = tid & 31, w = tid >> 5;
    const int r0 = lane >> 2, c0 = lane & 3;
    const int q0 = blockIdx.x * 128;
    const int bh = blockIdx.y, b = bh >> 4, h = bh & 15;
    const int use_mask = g_maskflag;

    const float* Kg0 = g_K + (size_t)bh * SS * HD;
    const float* Vg0 = g_V + (size_t)bh * SS * HD;

    // stage Q tile into Ps, pull fragments (2 m-tiles per warp)
    const float* Qg = g_Q + ((size_t)bh * SS + q0) * HD;
#pragma unroll
    for (int i = 0; i < 16; i++) {
        int c = tid + 128 * i;               // 0..2047
        int row = c >> 4, c4 = c & 15;
        *(float4*)&Ps[row * KST + c4 * 4] = *(const float4*)(Qg + (size_t)row * HD + c4 * 4);
    }
    __syncthreads();
    uint32_t qf[2][8][4];
#pragma unroll
    for (int mt = 0; mt < 2; mt++)
#pragma unroll
        for (int ks = 0; ks < 8; ks++) {
            const float* Qr = &Ps[(w * 32 + mt * 16 + r0) * KST + ks * 8 + c0];
            qf[mt][ks][0] = __float_as_uint(Qr[0]);
            qf[mt][ks][1] = __float_as_uint(Qr[8 * KST]);
            qf[mt][ks][2] = __float_as_uint(Qr[4]);
            qf[mt][ks][3] = __float_as_uint(Qr[8 * KST + 4]);
        }
    __syncthreads();

    float o[2][8][4];
#pragma unroll
    for (int mt = 0; mt < 2; mt++)
#pragma unroll
        for (int nt = 0; nt < 8; nt++)
#pragma unroll
            for (int j = 0; j < 4; j++) o[mt][nt][j] = 0.f;
    float mrow[2][2], lrow[2][2];
#pragma unroll
    for (int mt = 0; mt < 2; mt++) { mrow[mt][0] = mrow[mt][1] = -INFINITY;
                                     lrow[mt][0] = lrow[mt][1] = 0.f; }

    // K/V tile loader (32 rows x 64 floats each) via cp.async
    auto load_kv = [&](int t, int s) {
#pragma unroll
        for (int i = 0; i < 4; i++) {
            int c = tid + 128 * i;           // 0..511
            int row = c >> 4, c4 = c & 15;
            cp16(ks_b + (uint32_t)(s * KS_F + row * KST + c4 * 4) * 4,
                 Kg0 + (size_t)(t * 32 + row) * HD + c4 * 4);
            cp16(vs_b + (uint32_t)(s * VS_F + row * VST + c4 * 4) * 4,
                 Vg0 + (size_t)(t * 32 + row) * HD + c4 * 4);
        }
    };

    load_kv(0, 0); CP_COMMIT();

    const int NIT = SS / 32;                 // 64
    for (int it = 0; it < NIT; it++) {
        if (it + 1 < NIT) load_kv(it + 1, (it + 1) & 1);
        CP_COMMIT();
        asm volatile("cp.async.wait_group 1;" ::: "memory");
        __syncthreads();

        const float* Ksb = Ks + (it & 1) * KS_F;
        const float* Vsb = Vs + (it & 1) * VS_F;

        // S = Q @ K^T  (per warp: 32 x 32)
        float s[2][4][4];
#pragma unroll
        for (int mt = 0; mt < 2; mt++)
#pragma unroll
            for (int nt = 0; nt < 4; nt++)
#pragma unroll
                for (int j = 0; j < 4; j++) s[mt][nt][j] = 0.f;
#pragma unroll
        for (int nt = 0; nt < 4; nt++)
#pragma unroll
            for (int ks = 0; ks < 8; ks++) {
                const float* Kr = &Ksb[(nt * 8 + r0) * KST + ks * 8 + c0];
                uint32_t bb[2];
                bb[0] = __float_as_uint(Kr[0]);
                bb[1] = __float_as_uint(Kr[4]);
                mma_tf32(s[0][nt], qf[0][ks], bb);
                mma_tf32(s[1][nt], qf[1][ks], bb);
            }

        if (use_mask) {
#pragma unroll
            for (int mt = 0; mt < 2; mt++) {
                const float* Mg = mask + ((size_t)b * SS + (q0 + w * 32 + mt * 16 + r0)) * SS
                                       + it * 32;
#pragma unroll
                for (int nt = 0; nt < 4; nt++) {
                    float2 mlo = *(const float2*)(Mg + nt * 8 + 2 * c0);
                    float2 mhi = *(const float2*)(Mg + (size_t)8 * SS + nt * 8 + 2 * c0);
                    s[mt][nt][0] += mlo.x; s[mt][nt][1] += mlo.y;
                    s[mt][nt][2] += mhi.x; s[mt][nt][3] += mhi.y;
                }
            }
        }

        // online softmax + P store
#pragma unroll
        for (int mt = 0; mt < 2; mt++) {
            float mx_lo = -INFINITY, mx_hi = -INFINITY;
#pragma unroll
            for (int nt = 0; nt < 4; nt++) {
                mx_lo = fmaxf(mx_lo, fmaxf(s[mt][nt][0], s[mt][nt][1]));
                mx_hi = fmaxf(mx_hi, fmaxf(s[mt][nt][2], s[mt][nt][3]));
            }
            mx_lo = fmaxf(mx_lo, __shfl_xor_sync(0xffffffffu, mx_lo, 1));
            mx_lo = fmaxf(mx_lo, __shfl_xor_sync(0xffffffffu, mx_lo, 2));
            mx_hi = fmaxf(mx_hi, __shfl_xor_sync(0xffffffffu, mx_hi, 1));
            mx_hi = fmaxf(mx_hi, __shfl_xor_sync(0xffffffffu, mx_hi, 2));
            const float nm_lo = fmaxf(mrow[mt][0], mx_lo);
            const float nm_hi = fmaxf(mrow[mt][1], mx_hi);
            const float corr_lo = __expf(mrow[mt][0] - nm_lo);
            const float corr_hi = __expf(mrow[mt][1] - nm_hi);
            mrow[mt][0] = nm_lo; mrow[mt][1] = nm_hi;

            float sum_lo = 0.f, sum_hi = 0.f;
            float* Pw0 = &Ps[(w * 32 + mt * 16 + r0) * KST];
            float* Pw1 = Pw0 + 8 * KST;
#pragma unroll
            for (int nt = 0; nt < 4; nt++) {
                float p0 = __expf(s[mt][nt][0] - nm_lo);
                float p1 = __expf(s[mt][nt][1] - nm_lo);
                float p2 = __expf(s[mt][nt][2] - nm_hi);
                float p3 = __expf(s[mt][nt][3] - nm_hi);
                sum_lo += p0 + p1; sum_hi += p2 + p3;
                *(float2*)(Pw0 + nt * 8 + 2 * c0) = make_float2(rna_tf32(p0), rna_tf32(p1));
                *(float2*)(Pw1 + nt * 8 + 2 * c0) = make_float2(rna_tf32(p2), rna_tf32(p3));
            }
            sum_lo += __shfl_xor_sync(0xffffffffu, sum_lo, 1);
            sum_lo += __shfl_xor_sync(0xffffffffu, sum_lo, 2);
            sum_hi += __shfl_xor_sync(0xffffffffu, sum_hi, 1);
            sum_hi += __shfl_xor_sync(0xffffffffu, sum_hi, 2);
            lrow[mt][0] = lrow[mt][0] * corr_lo + sum_lo;
            lrow[mt][1] = lrow[mt][1] * corr_hi + sum_hi;
#pragma unroll
            for (int nt = 0; nt < 8; nt++) {
                o[mt][nt][0] *= corr_lo; o[mt][nt][1] *= corr_lo;
                o[mt][nt][2] *= corr_hi; o[mt][nt][3] *= corr_hi;
            }
        }
        __syncwarp();

        // O += P @ V  (per warp: 32 x 64, k=32)
#pragma unroll
        for (int kk = 0; kk < 4; kk++) {
            uint32_t aa[2][4];
#pragma unroll
            for (int mt = 0; mt < 2; mt++) {
                const float* Pr = &Ps[(w * 32 + mt * 16 + r0) * KST + kk * 8 + c0];
                aa[mt][0] = __float_as_uint(Pr[0]);
                aa[mt][1] = __float_as_uint(Pr[8 * KST]);
                aa[mt][2] = __float_as_uint(Pr[4]);
                aa[mt][3] = __float_as_uint(Pr[8 * KST + 4]);
            }
#pragma unroll
            for (int nt = 0; nt < 8; nt++) {
                uint32_t bb[2];
                bb[0] = __float_as_uint(Vsb[(kk * 8 + c0)     * VST + nt * 8 + r0]);
                bb[1] = __float_as_uint(Vsb[(kk * 8 + c0 + 4) * VST + nt * 8 + r0]);
                mma_tf32(o[0][nt], aa[0], bb);
                mma_tf32(o[1][nt], aa[1], bb);
            }
        }
        __syncthreads();   // all warps done with this K/V stage before reload
    }

    // epilogue: normalize, round, write Z[b*SS+q][h*HD+d]
#pragma unroll
    for (int mt = 0; mt < 2; mt++) {
        const float inv_lo = 1.f / lrow[mt][0], inv_hi = 1.f / lrow[mt][1];
        const int qlo = q0 + w * 32 + mt * 16 + r0;
        float* Zlo = g_Z + ((size_t)b * SS + qlo) * DIM + h * HD;
        float* Zhi = Zlo + (size_t)8 * DIM;
#pragma unroll
        for (int nt = 0; nt < 8; nt++) {
            const int d = nt * 8 + 2 * c0;
            *(float2*)(Zlo + d) = make_float2(rna_tf32(o[mt][nt][0] * inv_lo),
                                              rna_tf32(o[mt][nt][1] * inv_lo));
            *(float2*)(Zhi + d) = make_float2(rna_tf32(o[mt][nt][2] * inv_hi),
                                              rna_tf32(o[mt][nt][3] * inv_hi));
        }
    }
}

// ---------------------------------------------------------------------------
extern "C" void kernel_launch(void* const* d_in, const int* in_sizes, int n_in,
                              void* d_out, int out_size)
{
    const float* q    = (const float*)d_in[0];
    const float* k    = (const float*)d_in[1];
    const float* v    = (const float*)d_in[2];
    const float* mask = (const float*)d_in[3];
    const float* Wq   = (const float*)d_in[4];
    const float* Wk   = (const float*)d_in[5];
    const float* Wv   = (const float*)d_in[6];
    const float* Wd   = (const float*)d_in[7];

    float *gq, *gk, *gv, *gz, *rq, *rk, *rv;
    float (*rw)[DIM*DIM];
    cudaGetSymbolAddress((void**)&gq, g_Q);
    cudaGetSymbolAddress((void**)&gk, g_K);
    cudaGetSymbolAddress((void**)&gv, g_V);
    cudaGetSymbolAddress((void**)&gz, g_Z);
    cudaGetSymbolAddress((void**)&rq, g_RQ);
    cudaGetSymbolAddress((void**)&rk, g_RK);
    cudaGetSymbolAddress((void**)&rv, g_RV);
    cudaGetSymbolAddress((void**)&rw, g_RW);

    cudaFuncSetAttribute(gemm_mma<0,1>, cudaFuncAttributeMaxDynamicSharedMemorySize, GEMM_SMEM);
    cudaFuncSetAttribute(gemm_mma<1,0>, cudaFuncAttributeMaxDynamicSharedMemorySize, GEMM_SMEM);
    cudaFuncSetAttribute(attn_mma, cudaFuncAttributeMaxDynamicSharedMemorySize, ATTN_SMEM);

    const int NELT = MROWS * DIM;          // 8388608
    const int NW   = DIM * DIM;            // 1048576
    const int NM   = BB * SS * SS;         // 16777216

    reset_flag<<<1, 1>>>();
    scan_mask<<<NM/1024, 256>>>(mask);

    round_tf32<<<NELT/1024, 256>>>(q, rq);
    round_tf32<<<NELT/1024, 256>>>(k, rk);
    round_tf32<<<NELT/1024, 256>>>(v, rv);
    round_tf32<<<NW/1024, 256>>>(Wq, rw[0]);
    round_tf32<<<NW/1024, 256>>>(Wk, rw[1]);
    round_tf32<<<NW/1024, 256>>>(Wv, rw[2]);
    round_tf32<<<NW/1024, 256>>>(Wd, rw[3]);

    dim3 gp(MROWS/128, DIM/128);           // 64 x 8
    gemm_mma<0,1><<<gp, 128, GEMM_SMEM>>>(rq, rw[0], gq, 0.125f);  // fold 1/sqrt(64)
    gemm_mma<0,1><<<gp, 128, GEMM_SMEM>>>(rk, rw[1], gk, 1.0f);
    gemm_mma<0,1><<<gp, 128, GEMM_SMEM>>>(rv, rw[2], gv, 1.0f);

    attn_mma<<<dim3(SS/128, BB*NH), 128, ATTN_SMEM>>>(mask);

    gemm_mma<1,0><<<gp, 128, GEMM_SMEM>>>(gz, rw[3], (float*)d_out, 1.0f);
}

// round 5
// speedup vs baseline: 3.9297x; 1.0459x over previous
#include <cuda_runtime.h>
#include <math.h>
#include <stdint.h>

#define DIM 1024
#define BB 4
#define SS 2048
#define NH 16
#define HD 64
#define MROWS (BB*SS)   // 8192

// ---------------------------------------------------------------------------
// Scratch (device globals; no allocation allowed)
// ---------------------------------------------------------------------------
__device__ float g_Q[BB*NH*SS*HD];   // [b,h,s,d] projected Q (x 1/8), tf32-rounded
__device__ float g_K[BB*NH*SS*HD];
__device__ float g_V[BB*NH*SS*HD];
__device__ float g_Z[MROWS*DIM];     // attention out, tf32-rounded
__device__ int   g_maskflag;         // zero-initialized; reset by out_gemm each run

// ---------------------------------------------------------------------------
// Helpers (compute_103-legal, sm_80-era PTX only)
// ---------------------------------------------------------------------------
__device__ __forceinline__ uint32_t smem_u32(const void* p) {
    uint32_t a;
    asm("{ .reg .u64 t; cvta.to.shared.u64 t, %1; cvt.u32.u64 %0, t; }" : "=r"(a) : "l"(p));
    return a;
}
__device__ __forceinline__ void cp16(uint32_t dst, const void* src) {
    asm volatile("cp.async.cg.shared.global [%0], [%1], 16;" :: "r"(dst), "l"(src));
}
#define CP_COMMIT() asm volatile("cp.async.commit_group;" ::: "memory")

__device__ __forceinline__ float rna_tf32(float x) {
    uint32_t r;
    asm("cvt.rna.tf32.f32 %0, %1;" : "=r"(r) : "f"(x));
    return __uint_as_float(r);
}
// round-to-nearest tf32, result as raw b32 bits (mma operand)
__device__ __forceinline__ uint32_t tf32_bits(float x) {
    uint32_t r;
    asm("cvt.rna.tf32.f32 %0, %1;" : "=r"(r) : "f"(x));
    return r;
}

__device__ __forceinline__ void mma_tf32(float d[4], const uint32_t a[4], const uint32_t b[2]) {
    asm volatile(
        "mma.sync.aligned.m16n8k8.row.col.f32.tf32.tf32.f32 "
        "{%0,%1,%2,%3}, {%4,%5,%6,%7}, {%8,%9}, {%0,%1,%2,%3};"
        : "+f"(d[0]), "+f"(d[1]), "+f"(d[2]), "+f"(d[3])
        : "r"(a[0]), "r"(a[1]), "r"(a[2]), "r"(a[3]), "r"(b[0]), "r"(b[1]));
}

// ---------------------------------------------------------------------------
// GEMM core: C = scale * (A[M,K] @ W[N,K]^T), K=1024.
// BM=BN=128, BK=16, 128 threads (4 warps 2x2, warp tile 64x64), 4-stage pipe.
// Operand fragments are tf32-rounded in-register (RND_A for A; W always).
// LAYOUT 0: head layout  out[((b*NH+h)*SS+s)*HD+d];  LAYOUT 1: row-major.
// ---------------------------------------------------------------------------
#define PST 20                       // smem row stride (16 + 4 pad), floats
#define STG_F (2 * 128 * PST)        // A+B floats per stage = 5120
#define GEMM_SMEM (4 * STG_F * 4)    // 81920 bytes

template<int LAYOUT, int RND_A, int ROUND>
__device__ __forceinline__
void gemm_core(const float* __restrict__ A, const float* __restrict__ W,
               float* __restrict__ C, float scale, float* sm)
{
    const int tid = threadIdx.x;
    const int lane = tid & 31, wid = tid >> 5;
    const int wr = wid >> 1, wc = wid & 1;       // 2x2 warp grid, warp tile 64x64
    const int r0 = lane >> 2, c0 = lane & 3;
    const int row0 = blockIdx.x * 128, col0 = blockIdx.y * 128;
    const uint32_t smb = smem_u32(sm);

    float acc[4][8][4];
#pragma unroll
    for (int mt = 0; mt < 4; mt++)
#pragma unroll
        for (int nt = 0; nt < 8; nt++)
#pragma unroll
            for (int j = 0; j < 4; j++) acc[mt][nt][j] = 0.f;

    auto load_stage = [&](int kt, int s) {
        uint32_t a_s = smb + s * (STG_F * 4);
        uint32_t b_s = a_s + 128 * PST * 4;
#pragma unroll
        for (int i = 0; i < 4; i++) {
            int c = tid + 128 * i;               // 0..511
            int row = c >> 2, c4 = c & 3;
            uint32_t so = (uint32_t)(row * PST + c4 * 4) * 4;
            cp16(a_s + so, A + (size_t)(row0 + row) * DIM + kt * 16 + c4 * 4);
            cp16(b_s + so, W + (size_t)(col0 + row) * DIM + kt * 16 + c4 * 4);
        }
    };

    load_stage(0, 0); CP_COMMIT();
    load_stage(1, 1); CP_COMMIT();
    load_stage(2, 2); CP_COMMIT();

    const int NT = DIM / 16;                     // 64
    for (int kt = 0; kt < NT; kt++) {
        asm volatile("cp.async.wait_group 2;" ::: "memory");
        __syncthreads();
        if (kt + 3 < NT) load_stage(kt + 3, (kt + 3) & 3);
        CP_COMMIT();

        const float* As = sm + (kt & 3) * STG_F;
        const float* Bs = As + 128 * PST;
#pragma unroll
        for (int ks = 0; ks < 2; ks++) {
            const int kb = ks * 8;
            uint32_t a[4][4];
#pragma unroll
            for (int mt = 0; mt < 4; mt++) {
                const int R = wr * 64 + mt * 16;
                float a0 = As[(R + r0)     * PST + kb + c0];
                float a1 = As[(R + r0 + 8) * PST + kb + c0];
                float a2 = As[(R + r0)     * PST + kb + c0 + 4];
                float a3 = As[(R + r0 + 8) * PST + kb + c0 + 4];
                if (RND_A) {
                    a[mt][0] = tf32_bits(a0); a[mt][1] = tf32_bits(a1);
                    a[mt][2] = tf32_bits(a2); a[mt][3] = tf32_bits(a3);
                } else {
                    a[mt][0] = __float_as_uint(a0); a[mt][1] = __float_as_uint(a1);
                    a[mt][2] = __float_as_uint(a2); a[mt][3] = __float_as_uint(a3);
                }
            }
#pragma unroll
            for (int nt = 0; nt < 8; nt++) {
                const int Nb = wc * 64 + nt * 8;
                uint32_t b[2];
                b[0] = tf32_bits(Bs[(Nb + r0) * PST + kb + c0]);      // weights always rounded
                b[1] = tf32_bits(Bs[(Nb + r0) * PST + kb + c0 + 4]);
#pragma unroll
                for (int mt = 0; mt < 4; mt++)
                    mma_tf32(acc[mt][nt], a[mt], b);
            }
        }
    }

    const int h = (col0 + wc * 64) >> 6;
#pragma unroll
    for (int mt = 0; mt < 4; mt++) {
        const int rA = row0 + wr * 64 + mt * 16 + r0;
#pragma unroll
        for (int rr = 0; rr < 2; rr++) {
            const int r = rA + rr * 8;
#pragma unroll
            for (int nt = 0; nt < 8; nt++) {
                const int d = nt * 8 + 2 * c0;
                float v0 = acc[mt][nt][rr * 2 + 0] * scale;
                float v1 = acc[mt][nt][rr * 2 + 1] * scale;
                if (ROUND) { v0 = rna_tf32(v0); v1 = rna_tf32(v1); }
                float2 val = make_float2(v0, v1);
                if (LAYOUT == 0) {
                    const int b = r >> 11, s = r & (SS - 1);
                    *(float2*)(C + ((size_t)((b * NH + h) * SS) + s) * HD + d) = val;
                } else {
                    *(float2*)(C + (size_t)r * DIM + col0 + wc * 64 + d) = val;
                }
            }
        }
    }
}

// ---------------------------------------------------------------------------
// Merged QKV projection + mask scan.  grid (64, 8, 4); z=0/1/2 GEMM, z=3 scan.
// ---------------------------------------------------------------------------
__global__ __launch_bounds__(128, 2)
void qkv_gemm(const float* __restrict__ q, const float* __restrict__ k,
              const float* __restrict__ v, const float* __restrict__ Wq,
              const float* __restrict__ Wk, const float* __restrict__ Wv,
              const float* __restrict__ mask)
{
    extern __shared__ float sm[];
    const int z = blockIdx.z;
    if (z == 3) {
        // mask scan: 512 CTAs x 128 threads x 64 float4 = 16.7M floats
        const float4* m4 = (const float4*)mask;
        const int cta = blockIdx.y * gridDim.x + blockIdx.x;      // 0..511
        const size_t base = (size_t)cta * 8192 + threadIdx.x;
        bool nz = false;
#pragma unroll 8
        for (int i = 0; i < 64; i++) {
            float4 vv = m4[base + (size_t)i * 128];
            nz |= (vv.x != 0.f) | (vv.y != 0.f) | (vv.z != 0.f) | (vv.w != 0.f);
        }
        if (__syncthreads_or(nz) && threadIdx.x == 0)
            atomicExch(&g_maskflag, 1);
        return;
    }
    const float* A = (z == 0) ? q : (z == 1) ? k : v;
    const float* W = (z == 0) ? Wq : (z == 1) ? Wk : Wv;
    float* C = (z == 0) ? g_Q : (z == 1) ? g_K : g_V;
    gemm_core<0, 1, 1>(A, W, C, (z == 0) ? 0.125f : 1.0f, sm);
}

// ---------------------------------------------------------------------------
// Output projection + maskflag reset (for the next graph replay).
// ---------------------------------------------------------------------------
__global__ __launch_bounds__(128, 2)
void out_gemm(const float* __restrict__ Wd, float* __restrict__ C)
{
    extern __shared__ float sm[];
    gemm_core<1, 0, 0>(g_Z, Wd, C, 1.0f, sm);
    if (blockIdx.x == 0 && blockIdx.y == 0 && threadIdx.x == 0)
        g_maskflag = 0;
}

// ---------------------------------------------------------------------------
// mma.sync tf32 flash attention (round-4 structure).
// CTA: 128 thr (4 warps), 128 q-rows (32/warp, mt=2), 64 iters of 32 keys.
// K/V double-buffered via cp.async. P staged per-warp through smem.
// ---------------------------------------------------------------------------
#define KST 68
#define VST 72
#define KS_F (32 * KST)
#define VS_F (32 * VST)
#define ATTN_SMEM ((2*KS_F + 2*VS_F + 128*KST) * 4)   // 70656 B

__global__ __launch_bounds__(128, 2)
void attn_mma(const float* __restrict__ mask)
{
    extern __shared__ float sm[];
    float* Ks = sm;
    float* Vs = sm + 2 * KS_F;
    float* Ps = sm + 2 * KS_F + 2 * VS_F;
    const uint32_t ks_b = smem_u32(Ks);
    const uint32_t vs_b = smem_u32(Vs);

    const int tid = threadIdx.x, lane = tid & 31, w = tid >> 5;
    const int r0 = lane >> 2, c0 = lane & 3;
    const int q0 = blockIdx.x * 128;
    const int bh = blockIdx.y, b = bh >> 4, h = bh & 15;
    const int use_mask = g_maskflag;

    const float* Kg0 = g_K + (size_t)bh * SS * HD;
    const float* Vg0 = g_V + (size_t)bh * SS * HD;

    const float* Qg = g_Q + ((size_t)bh * SS + q0) * HD;
#pragma unroll
    for (int i = 0; i < 16; i++) {
        int c = tid + 128 * i;
        int row = c >> 4, c4 = c & 15;
        *(float4*)&Ps[row * KST + c4 * 4] = *(const float4*)(Qg + (size_t)row * HD + c4 * 4);
    }
    __syncthreads();
    uint32_t qf[2][8][4];
#pragma unroll
    for (int mt = 0; mt < 2; mt++)
#pragma unroll
        for (int ks = 0; ks < 8; ks++) {
            const float* Qr = &Ps[(w * 32 + mt * 16 + r0) * KST + ks * 8 + c0];
            qf[mt][ks][0] = __float_as_uint(Qr[0]);
            qf[mt][ks][1] = __float_as_uint(Qr[8 * KST]);
            qf[mt][ks][2] = __float_as_uint(Qr[4]);
            qf[mt][ks][3] = __float_as_uint(Qr[8 * KST + 4]);
        }
    __syncthreads();

    float o[2][8][4];
#pragma unroll
    for (int mt = 0; mt < 2; mt++)
#pragma unroll
        for (int nt = 0; nt < 8; nt++)
#pragma unroll
            for (int j = 0; j < 4; j++) o[mt][nt][j] = 0.f;
    float mrow[2][2], lrow[2][2];
#pragma unroll
    for (int mt = 0; mt < 2; mt++) { mrow[mt][0] = mrow[mt][1] = -INFINITY;
                                     lrow[mt][0] = lrow[mt][1] = 0.f; }

    auto load_kv = [&](int t, int s) {
#pragma unroll
        for (int i = 0; i < 4; i++) {
            int c = tid + 128 * i;
            int row = c >> 4, c4 = c & 15;
            cp16(ks_b + (uint32_t)(s * KS_F + row * KST + c4 * 4) * 4,
                 Kg0 + (size_t)(t * 32 + row) * HD + c4 * 4);
            cp16(vs_b + (uint32_t)(s * VS_F + row * VST + c4 * 4) * 4,
                 Vg0 + (size_t)(t * 32 + row) * HD + c4 * 4);
        }
    };

    load_kv(0, 0); CP_COMMIT();

    const int NIT = SS / 32;
    for (int it = 0; it < NIT; it++) {
        if (it + 1 < NIT) load_kv(it + 1, (it + 1) & 1);
        CP_COMMIT();
        asm volatile("cp.async.wait_group 1;" ::: "memory");
        __syncthreads();

        const float* Ksb = Ks + (it & 1) * KS_F;
        const float* Vsb = Vs + (it & 1) * VS_F;

        float s[2][4][4];
#pragma unroll
        for (int mt = 0; mt < 2; mt++)
#pragma unroll
            for (int nt = 0; nt < 4; nt++)
#pragma unroll
                for (int j = 0; j < 4; j++) s[mt][nt][j] = 0.f;
#pragma unroll
        for (int nt = 0; nt < 4; nt++)
#pragma unroll
            for (int ks = 0; ks < 8; ks++) {
                const float* Kr = &Ksb[(nt * 8 + r0) * KST + ks * 8 + c0];
                uint32_t bb[2];
                bb[0] = __float_as_uint(Kr[0]);
                bb[1] = __float_as_uint(Kr[4]);
                mma_tf32(s[0][nt], qf[0][ks], bb);
                mma_tf32(s[1][nt], qf[1][ks], bb);
            }

        if (use_mask) {
#pragma unroll
            for (int mt = 0; mt < 2; mt++) {
                const float* Mg = mask + ((size_t)b * SS + (q0 + w * 32 + mt * 16 + r0)) * SS
                                       + it * 32;
#pragma unroll
                for (int nt = 0; nt < 4; nt++) {
                    float2 mlo = *(const float2*)(Mg + nt * 8 + 2 * c0);
                    float2 mhi = *(const float2*)(Mg + (size_t)8 * SS + nt * 8 + 2 * c0);
                    s[mt][nt][0] += mlo.x; s[mt][nt][1] += mlo.y;
                    s[mt][nt][2] += mhi.x; s[mt][nt][3] += mhi.y;
                }
            }
        }

#pragma unroll
        for (int mt = 0; mt < 2; mt++) {
            float mx_lo = -INFINITY, mx_hi = -INFINITY;
#pragma unroll
            for (int nt = 0; nt < 4; nt++) {
                mx_lo = fmaxf(mx_lo, fmaxf(s[mt][nt][0], s[mt][nt][1]));
                mx_hi = fmaxf(mx_hi, fmaxf(s[mt][nt][2], s[mt][nt][3]));
            }
            mx_lo = fmaxf(mx_lo, __shfl_xor_sync(0xffffffffu, mx_lo, 1));
            mx_lo = fmaxf(mx_lo, __shfl_xor_sync(0xffffffffu, mx_lo, 2));
            mx_hi = fmaxf(mx_hi, __shfl_xor_sync(0xffffffffu, mx_hi, 1));
            mx_hi = fmaxf(mx_hi, __shfl_xor_sync(0xffffffffu, mx_hi, 2));
            const float nm_lo = fmaxf(mrow[mt][0], mx_lo);
            const float nm_hi = fmaxf(mrow[mt][1], mx_hi);
            const float corr_lo = __expf(mrow[mt][0] - nm_lo);
            const float corr_hi = __expf(mrow[mt][1] - nm_hi);
            mrow[mt][0] = nm_lo; mrow[mt][1] = nm_hi;

            float sum_lo = 0.f, sum_hi = 0.f;
            float* Pw0 = &Ps[(w * 32 + mt * 16 + r0) * KST];
            float* Pw1 = Pw0 + 8 * KST;
#pragma unroll
            for (int nt = 0; nt < 4; nt++) {
                float p0 = __expf(s[mt][nt][0] - nm_lo);
                float p1 = __expf(s[mt][nt][1] - nm_lo);
                float p2 = __expf(s[mt][nt][2] - nm_hi);
                float p3 = __expf(s[mt][nt][3] - nm_hi);
                sum_lo += p0 + p1; sum_hi += p2 + p3;
                *(float2*)(Pw0 + nt * 8 + 2 * c0) = make_float2(rna_tf32(p0), rna_tf32(p1));
                *(float2*)(Pw1 + nt * 8 + 2 * c0) = make_float2(rna_tf32(p2), rna_tf32(p3));
            }
            sum_lo += __shfl_xor_sync(0xffffffffu, sum_lo, 1);
            sum_lo += __shfl_xor_sync(0xffffffffu, sum_lo, 2);
            sum_hi += __shfl_xor_sync(0xffffffffu, sum_hi, 1);
            sum_hi += __shfl_xor_sync(0xffffffffu, sum_hi, 2);
            lrow[mt][0] = lrow[mt][0] * corr_lo + sum_lo;
            lrow[mt][1] = lrow[mt][1] * corr_hi + sum_hi;
#pragma unroll
            for (int nt = 0; nt < 8; nt++) {
                o[mt][nt][0] *= corr_lo; o[mt][nt][1] *= corr_lo;
                o[mt][nt][2] *= corr_hi; o[mt][nt][3] *= corr_hi;
            }
        }
        __syncwarp();

#pragma unroll
        for (int kk = 0; kk < 4; kk++) {
            uint32_t aa[2][4];
#pragma unroll
            for (int mt = 0; mt < 2; mt++) {
                const float* Pr = &Ps[(w * 32 + mt * 16 + r0) * KST + kk * 8 + c0];
                aa[mt][0] = __float_as_uint(Pr[0]);
                aa[mt][1] = __float_as_uint(Pr[8 * KST]);
                aa[mt][2] = __float_as_uint(Pr[4]);
                aa[mt][3] = __float_as_uint(Pr[8 * KST + 4]);
            }
#pragma unroll
            for (int nt = 0; nt < 8; nt++) {
                uint32_t bb[2];
                bb[0] = __float_as_uint(Vsb[(kk * 8 + c0)     * VST + nt * 8 + r0]);
                bb[1] = __float_as_uint(Vsb[(kk * 8 + c0 + 4) * VST + nt * 8 + r0]);
                mma_tf32(o[0][nt], aa[0], bb);
                mma_tf32(o[1][nt], aa[1], bb);
            }
        }
        __syncthreads();
    }

#pragma unroll
    for (int mt = 0; mt < 2; mt++) {
        const float inv_lo = 1.f / lrow[mt][0], inv_hi = 1.f / lrow[mt][1];
        const int qlo = q0 + w * 32 + mt * 16 + r0;
        float* Zlo = g_Z + ((size_t)b * SS + qlo) * DIM + h * HD;
        float* Zhi = Zlo + (size_t)8 * DIM;
#pragma unroll
        for (int nt = 0; nt < 8; nt++) {
            const int d = nt * 8 + 2 * c0;
            *(float2*)(Zlo + d) = make_float2(rna_tf32(o[mt][nt][0] * inv_lo),
                                              rna_tf32(o[mt][nt][1] * inv_lo));
            *(float2*)(Zhi + d) = make_float2(rna_tf32(o[mt][nt][2] * inv_hi),
                                              rna_tf32(o[mt][nt][3] * inv_hi));
        }
    }
}

// ---------------------------------------------------------------------------
extern "C" void kernel_launch(void* const* d_in, const int* in_sizes, int n_in,
                              void* d_out, int out_size)
{
    const float* q    = (const float*)d_in[0];
    const float* k    = (const float*)d_in[1];
    const float* v    = (const float*)d_in[2];
    const float* mask = (const float*)d_in[3];
    const float* Wq   = (const float*)d_in[4];
    const float* Wk   = (const float*)d_in[5];
    const float* Wv   = (const float*)d_in[6];
    const float* Wd   = (const float*)d_in[7];

    cudaFuncSetAttribute(qkv_gemm, cudaFuncAttributeMaxDynamicSharedMemorySize, GEMM_SMEM);
    cudaFuncSetAttribute(out_gemm, cudaFuncAttributeMaxDynamicSharedMemorySize, GEMM_SMEM);
    cudaFuncSetAttribute(attn_mma, cudaFuncAttributeMaxDynamicSharedMemorySize, ATTN_SMEM);

    // launch 1: q/k/v projections (z=0..2) + mask scan (z=3)
    qkv_gemm<<<dim3(MROWS/128, DIM/128, 4), 128, GEMM_SMEM>>>(q, k, v, Wq, Wk, Wv, mask);

    // launch 2: flash attention (tf32 mma), writes tf32-rounded Z
    attn_mma<<<dim3(SS/128, BB*NH), 128, ATTN_SMEM>>>(mask);

    // launch 3: output projection (+ maskflag reset for next replay)
    out_gemm<<<dim3(MROWS/128, DIM/128), 128, GEMM_SMEM>>>(Wd, (float*)d_out);
}

// round 6
// speedup vs baseline: 4.5222x; 1.1508x over previous
#include <cuda_runtime.h>
#include <math.h>
#include <stdint.h>

#define DIM 1024
#define BB 4
#define SS 2048
#define NH 16
#define HD 64
#define MROWS (BB*SS)   // 8192

// ---------------------------------------------------------------------------
// Scratch (device globals; no allocation allowed)
// ---------------------------------------------------------------------------
__device__ float g_Q[BB*NH*SS*HD];   // [b,h,s,d] projected Q (x 1/8), tf32-rounded
__device__ float g_K[BB*NH*SS*HD];
__device__ float g_V[BB*NH*SS*HD];
__device__ float g_Z[MROWS*DIM];     // attention out, tf32-rounded
__device__ float g_RQ[MROWS*DIM];    // tf32-rounded inputs
__device__ float g_RK[MROWS*DIM];
__device__ float g_RV[MROWS*DIM];
__device__ float g_RW[4][DIM*DIM];   // tf32-rounded weights
__device__ int   g_maskflag;         // zero-init; reset by out_gemm each run

// ---------------------------------------------------------------------------
// Helpers (compute_103-legal)
// ---------------------------------------------------------------------------
__device__ __forceinline__ uint32_t smem_u32(const void* p) {
    uint32_t a;
    asm("{ .reg .u64 t; cvta.to.shared.u64 t, %1; cvt.u32.u64 %0, t; }" : "=r"(a) : "l"(p));
    return a;
}
__device__ __forceinline__ void cp16(uint32_t dst, const void* src) {
    asm volatile("cp.async.cg.shared.global [%0], [%1], 16;" :: "r"(dst), "l"(src));
}
#define CP_COMMIT() asm volatile("cp.async.commit_group;" ::: "memory")

__device__ __forceinline__ float rna_tf32(float x) {
    uint32_t r;
    asm("cvt.rna.tf32.f32 %0, %1;" : "=r"(r) : "f"(x));
    return __uint_as_float(r);
}
__device__ __forceinline__ void mma_tf32(float d[4], const uint32_t a[4], const uint32_t b[2]) {
    asm volatile(
        "mma.sync.aligned.m16n8k8.row.col.f32.tf32.tf32.f32 "
        "{%0,%1,%2,%3}, {%4,%5,%6,%7}, {%8,%9}, {%0,%1,%2,%3};"
        : "+f"(d[0]), "+f"(d[1]), "+f"(d[2]), "+f"(d[3])
        : "r"(a[0]), "r"(a[1]), "r"(a[2]), "r"(a[3]), "r"(b[0]), "r"(b[1]));
}
// ldmatrix x4: four 8x8 b16 matrices == four 8x4 f32 blocks; thread t gets
// f32 element (t/4, t%4) of matrix i in reg i.
__device__ __forceinline__ void ldsm_x4(uint32_t r[4], uint32_t addr) {
    asm volatile("ldmatrix.sync.aligned.m8n8.x4.shared.b16 {%0,%1,%2,%3}, [%4];"
                 : "=r"(r[0]), "=r"(r[1]), "=r"(r[2]), "=r"(r[3]) : "r"(addr));
}

// ---------------------------------------------------------------------------
// Merged pre-round (q,k,v,W*) + mask scan. grid (4096,1,8), 256 thr.
// Each active thread rounds 4 float4 (independent -> MLP=8).
// ---------------------------------------------------------------------------
__global__ __launch_bounds__(256)
void round_all(const float* __restrict__ q, const float* __restrict__ k,
               const float* __restrict__ v, const float* __restrict__ Wq,
               const float* __restrict__ Wk, const float* __restrict__ Wv,
               const float* __restrict__ Wd, const float* __restrict__ mask)
{
    const int z = blockIdx.z;
    const int tid = threadIdx.x;
    if (z == 7) {   // mask scan: 4096 blocks x 256 thr x 4 float4 = 16.7M floats
        const float4* m4 = (const float4*)mask;
        const size_t base = (size_t)blockIdx.x * 1024 + tid;
        bool nz = false;
#pragma unroll
        for (int i = 0; i < 4; i++) {
            float4 vv = m4[base + (size_t)i * 256];
            nz |= (vv.x != 0.f) | (vv.y != 0.f) | (vv.z != 0.f) | (vv.w != 0.f);
        }
        if (__syncthreads_or(nz) && tid == 0) atomicExch(&g_maskflag, 1);
        return;
    }
    const float* src; float* dst; int nblk;
    switch (z) {
        case 0: src = q;  dst = g_RQ;    nblk = 2048; break;
        case 1: src = k;  dst = g_RK;    nblk = 2048; break;
        case 2: src = v;  dst = g_RV;    nblk = 2048; break;
        case 3: src = Wq; dst = g_RW[0]; nblk = 256;  break;
        case 4: src = Wk; dst = g_RW[1]; nblk = 256;  break;
        case 5: src = Wv; dst = g_RW[2]; nblk = 256;  break;
        default: src = Wd; dst = g_RW[3]; nblk = 256; break;
    }
    if (blockIdx.x >= (unsigned)nblk) return;
    const float4* s4 = (const float4*)src;
    float4* d4 = (float4*)dst;
    const size_t base = (size_t)blockIdx.x * 1024 + tid;
    float4 vv[4];
#pragma unroll
    for (int i = 0; i < 4; i++) vv[i] = s4[base + (size_t)i * 256];
#pragma unroll
    for (int i = 0; i < 4; i++) {
        vv[i].x = rna_tf32(vv[i].x); vv[i].y = rna_tf32(vv[i].y);
        vv[i].z = rna_tf32(vv[i].z); vv[i].w = rna_tf32(vv[i].w);
        d4[base + (size_t)i * 256] = vv[i];
    }
}

// ---------------------------------------------------------------------------
// GEMM core: C = scale * (A[M,K] @ W[N,K]^T), K=1024. Operands pre-rounded.
// BM=BN=128, BK=16, 128 threads (4 warps 2x2, warp tile 64x64), 4-stage pipe.
// Fragments via ldmatrix.x4.
// ---------------------------------------------------------------------------
#define PST 20                       // smem row stride (16 + 4 pad), floats
#define STG_F (2 * 128 * PST)        // A+B floats per stage = 5120
#define GEMM_SMEM (4 * STG_F * 4)    // 81920 bytes

template<int LAYOUT, int ROUND>
__device__ __forceinline__
void gemm_core(const float* __restrict__ A, const float* __restrict__ W,
               float* __restrict__ C, float scale, float* sm)
{
    const int tid = threadIdx.x;
    const int lane = tid & 31, wid = tid >> 5;
    const int wr = wid >> 1, wc = wid & 1;       // 2x2 warp grid, warp tile 64x64
    const int r0 = lane >> 2, c0 = lane & 3;
    const int g = lane >> 3, lr = lane & 7;
    const int row0 = blockIdx.x * 128, col0 = blockIdx.y * 128;
    const uint32_t smb = smem_u32(sm);

    // ldsm address offsets (floats), constant per thread
    // A-style: reg1 = row+8 (g&1), reg2 = col+4 (g>>1)
    const int aoff = (wr * 64 + lr + (g & 1) * 8) * PST + (g >> 1) * 4;
    // B-style: reg1 = col+4 (g&1), reg2 = row+8 (g>>1)
    const int boff = (wc * 64 + lr + (g >> 1) * 8) * PST + (g & 1) * 4;

    float acc[4][8][4];
#pragma unroll
    for (int mt = 0; mt < 4; mt++)
#pragma unroll
        for (int nt = 0; nt < 8; nt++)
#pragma unroll
            for (int j = 0; j < 4; j++) acc[mt][nt][j] = 0.f;

    auto load_stage = [&](int kt, int s) {
        uint32_t a_s = smb + s * (STG_F * 4);
        uint32_t b_s = a_s + 128 * PST * 4;
#pragma unroll
        for (int i = 0; i < 4; i++) {
            int c = tid + 128 * i;               // 0..511
            int row = c >> 2, c4 = c & 3;
            uint32_t so = (uint32_t)(row * PST + c4 * 4) * 4;
            cp16(a_s + so, A + (size_t)(row0 + row) * DIM + kt * 16 + c4 * 4);
            cp16(b_s + so, W + (size_t)(col0 + row) * DIM + kt * 16 + c4 * 4);
        }
    };

    load_stage(0, 0); CP_COMMIT();
    load_stage(1, 1); CP_COMMIT();
    load_stage(2, 2); CP_COMMIT();

    const int NT = DIM / 16;                     // 64
    for (int kt = 0; kt < NT; kt++) {
        asm volatile("cp.async.wait_group 2;" ::: "memory");
        __syncthreads();
        if (kt + 3 < NT) load_stage(kt + 3, (kt + 3) & 3);
        CP_COMMIT();

        const uint32_t a_s = smb + (kt & 3) * (STG_F * 4);
        const uint32_t b_s = a_s + 128 * PST * 4;
#pragma unroll
        for (int ks = 0; ks < 2; ks++) {
            const int kb = ks * 8;
            uint32_t a[4][4];
#pragma unroll
            for (int mt = 0; mt < 4; mt++)
                ldsm_x4(a[mt], a_s + (uint32_t)(aoff + mt * 16 * PST + kb) * 4);
            uint32_t bp[4][4];                   // pair p covers nt=2p, 2p+1
#pragma unroll
            for (int p = 0; p < 4; p++)
                ldsm_x4(bp[p], b_s + (uint32_t)(boff + p * 16 * PST + kb) * 4);
#pragma unroll
            for (int nt = 0; nt < 8; nt++) {
                const uint32_t bfr[2] = { bp[nt >> 1][(nt & 1) * 2],
                                          bp[nt >> 1][(nt & 1) * 2 + 1] };
#pragma unroll
                for (int mt = 0; mt < 4; mt++)
                    mma_tf32(acc[mt][nt], a[mt], bfr);
            }
        }
    }

    const int h = (col0 + wc * 64) >> 6;
#pragma unroll
    for (int mt = 0; mt < 4; mt++) {
        const int rA = row0 + wr * 64 + mt * 16 + r0;
#pragma unroll
        for (int rr = 0; rr < 2; rr++) {
            const int r = rA + rr * 8;
#pragma unroll
            for (int nt = 0; nt < 8; nt++) {
                const int d = nt * 8 + 2 * c0;
                float v0 = acc[mt][nt][rr * 2 + 0] * scale;
                float v1 = acc[mt][nt][rr * 2 + 1] * scale;
                if (ROUND) { v0 = rna_tf32(v0); v1 = rna_tf32(v1); }
                float2 val = make_float2(v0, v1);
                if (LAYOUT == 0) {
                    const int b = r >> 11, s = r & (SS - 1);
                    *(float2*)(C + ((size_t)((b * NH + h) * SS) + s) * HD + d) = val;
                } else {
                    *(float2*)(C + (size_t)r * DIM + col0 + wc * 64 + d) = val;
                }
            }
        }
    }
}

__global__ __launch_bounds__(128, 2)
void qkv_gemm()
{
    extern __shared__ float sm[];
    const int z = blockIdx.z;
    const float* A = (z == 0) ? g_RQ : (z == 1) ? g_RK : g_RV;
    const float* W = g_RW[z];
    float* C = (z == 0) ? g_Q : (z == 1) ? g_K : g_V;
    gemm_core<0, 1>(A, W, C, (z == 0) ? 0.125f : 1.0f, sm);
}

__global__ __launch_bounds__(128, 2)
void out_gemm(float* __restrict__ C)
{
    extern __shared__ float sm[];
    gemm_core<1, 0>(g_Z, g_RW[3], C, 1.0f, sm);
    if (blockIdx.x == 0 && blockIdx.y == 0 && threadIdx.x == 0)
        g_maskflag = 0;   // for the next graph replay
}

// ---------------------------------------------------------------------------
// mma.sync tf32 flash attention, LDSM fragments for K and P.
// CTA: 128 thr (4 warps), 128 q-rows (32/warp, mt=2), 64 iters of 32 keys.
// ---------------------------------------------------------------------------
#define KST 68
#define VST 72
#define KS_F (32 * KST)
#define VS_F (32 * VST)
#define ATTN_SMEM ((2*KS_F + 2*VS_F + 128*KST) * 4)   // 70656 B

__global__ __launch_bounds__(128, 2)
void attn_mma(const float* __restrict__ mask)
{
    extern __shared__ float sm[];
    float* Ks = sm;
    float* Vs = sm + 2 * KS_F;
    float* Ps = sm + 2 * KS_F + 2 * VS_F;
    const uint32_t ks_b = smem_u32(Ks);
    const uint32_t vs_b = smem_u32(Vs);
    const uint32_t ps_b = smem_u32(Ps);

    const int tid = threadIdx.x, lane = tid & 31, w = tid >> 5;
    const int r0 = lane >> 2, c0 = lane & 3;
    const int g = lane >> 3, lr = lane & 7;
    const int q0 = blockIdx.x * 128;
    const int bh = blockIdx.y, b = bh >> 4, h = bh & 15;
    const int use_mask = g_maskflag;

    // ldsm offsets (floats)
    const int pAoff = (w * 32 + lr + (g & 1) * 8) * KST + (g >> 1) * 4;  // A-style, P
    const int kBoff = (lr + (g >> 1) * 8) * KST + (g & 1) * 4;           // B-style, K

    const float* Kg0 = g_K + (size_t)bh * SS * HD;
    const float* Vg0 = g_V + (size_t)bh * SS * HD;

    const float* Qg = g_Q + ((size_t)bh * SS + q0) * HD;
#pragma unroll
    for (int i = 0; i < 16; i++) {
        int c = tid + 128 * i;
        int row = c >> 4, c4 = c & 15;
        *(float4*)&Ps[row * KST + c4 * 4] = *(const float4*)(Qg + (size_t)row * HD + c4 * 4);
    }
    __syncthreads();
    uint32_t qf[2][8][4];
#pragma unroll
    for (int mt = 0; mt < 2; mt++)
#pragma unroll
        for (int ks = 0; ks < 8; ks++)
            ldsm_x4(qf[mt][ks], ps_b + (uint32_t)(pAoff + mt * 16 * KST + ks * 8) * 4);
    __syncthreads();

    float o[2][8][4];
#pragma unroll
    for (int mt = 0; mt < 2; mt++)
#pragma unroll
        for (int nt = 0; nt < 8; nt++)
#pragma unroll
            for (int j = 0; j < 4; j++) o[mt][nt][j] = 0.f;
    float mrow[2][2], lrow[2][2];
#pragma unroll
    for (int mt = 0; mt < 2; mt++) { mrow[mt][0] = mrow[mt][1] = -INFINITY;
                                     lrow[mt][0] = lrow[mt][1] = 0.f; }

    auto load_kv = [&](int t, int s) {
#pragma unroll
        for (int i = 0; i < 4; i++) {
            int c = tid + 128 * i;
            int row = c >> 4, c4 = c & 15;
            cp16(ks_b + (uint32_t)(s * KS_F + row * KST + c4 * 4) * 4,
                 Kg0 + (size_t)(t * 32 + row) * HD + c4 * 4);
            cp16(vs_b + (uint32_t)(s * VS_F + row * VST + c4 * 4) * 4,
                 Vg0 + (size_t)(t * 32 + row) * HD + c4 * 4);
        }
    };

    load_kv(0, 0); CP_COMMIT();

    const int NIT = SS / 32;
    for (int it = 0; it < NIT; it++) {
        if (it + 1 < NIT) load_kv(it + 1, (it + 1) & 1);
        CP_COMMIT();
        asm volatile("cp.async.wait_group 1;" ::: "memory");
        __syncthreads();

        const uint32_t ksb = ks_b + (uint32_t)((it & 1) * KS_F) * 4;
        const float* Vsb = Vs + (it & 1) * VS_F;

        // S = Q @ K^T  (per warp: 32 x 32)
        float s[2][4][4];
#pragma unroll
        for (int mt = 0; mt < 2; mt++)
#pragma unroll
            for (int nt = 0; nt < 4; nt++)
#pragma unroll
                for (int j = 0; j < 4; j++) s[mt][nt][j] = 0.f;
#pragma unroll
        for (int ks = 0; ks < 8; ks++) {
            uint32_t kp[2][4];                   // pair p covers nt=2p, 2p+1
            ldsm_x4(kp[0], ksb + (uint32_t)(kBoff + ks * 8) * 4);
            ldsm_x4(kp[1], ksb + (uint32_t)(kBoff + 16 * KST + ks * 8) * 4);
#pragma unroll
            for (int nt = 0; nt < 4; nt++) {
                const uint32_t bfr[2] = { kp[nt >> 1][(nt & 1) * 2],
                                          kp[nt >> 1][(nt & 1) * 2 + 1] };
                mma_tf32(s[0][nt], qf[0][ks], bfr);
                mma_tf32(s[1][nt], qf[1][ks], bfr);
            }
        }

        if (use_mask) {
#pragma unroll
            for (int mt = 0; mt < 2; mt++) {
                const float* Mg = mask + ((size_t)b * SS + (q0 + w * 32 + mt * 16 + r0)) * SS
                                       + it * 32;
#pragma unroll
                for (int nt = 0; nt < 4; nt++) {
                    float2 mlo = *(const float2*)(Mg + nt * 8 + 2 * c0);
                    float2 mhi = *(const float2*)(Mg + (size_t)8 * SS + nt * 8 + 2 * c0);
                    s[mt][nt][0] += mlo.x; s[mt][nt][1] += mlo.y;
                    s[mt][nt][2] += mhi.x; s[mt][nt][3] += mhi.y;
                }
            }
        }

        // online softmax + P store (tf32-rounded)
#pragma unroll
        for (int mt = 0; mt < 2; mt++) {
            float mx_lo = -INFINITY, mx_hi = -INFINITY;
#pragma unroll
            for (int nt = 0; nt < 4; nt++) {
                mx_lo = fmaxf(mx_lo, fmaxf(s[mt][nt][0], s[mt][nt][1]));
                mx_hi = fmaxf(mx_hi, fmaxf(s[mt][nt][2], s[mt][nt][3]));
            }
            mx_lo = fmaxf(mx_lo, __shfl_xor_sync(0xffffffffu, mx_lo, 1));
            mx_lo = fmaxf(mx_lo, __shfl_xor_sync(0xffffffffu, mx_lo, 2));
            mx_hi = fmaxf(mx_hi, __shfl_xor_sync(0xffffffffu, mx_hi, 1));
            mx_hi = fmaxf(mx_hi, __shfl_xor_sync(0xffffffffu, mx_hi, 2));
            const float nm_lo = fmaxf(mrow[mt][0], mx_lo);
            const float nm_hi = fmaxf(mrow[mt][1], mx_hi);
            const float corr_lo = __expf(mrow[mt][0] - nm_lo);
            const float corr_hi = __expf(mrow[mt][1] - nm_hi);
            mrow[mt][0] = nm_lo; mrow[mt][1] = nm_hi;

            float sum_lo = 0.f, sum_hi = 0.f;
            float* Pw0 = &Ps[(w * 32 + mt * 16 + r0) * KST];
            float* Pw1 = Pw0 + 8 * KST;
#pragma unroll
            for (int nt = 0; nt < 4; nt++) {
                float p0 = __expf(s[mt][nt][0] - nm_lo);
                float p1 = __expf(s[mt][nt][1] - nm_lo);
                float p2 = __expf(s[mt][nt][2] - nm_hi);
                float p3 = __expf(s[mt][nt][3] - nm_hi);
                sum_lo += p0 + p1; sum_hi += p2 + p3;
                *(float2*)(Pw0 + nt * 8 + 2 * c0) = make_float2(rna_tf32(p0), rna_tf32(p1));
                *(float2*)(Pw1 + nt * 8 + 2 * c0) = make_float2(rna_tf32(p2), rna_tf32(p3));
            }
            sum_lo += __shfl_xor_sync(0xffffffffu, sum_lo, 1);
            sum_lo += __shfl_xor_sync(0xffffffffu, sum_lo, 2);
            sum_hi += __shfl_xor_sync(0xffffffffu, sum_hi, 1);
            sum_hi += __shfl_xor_sync(0xffffffffu, sum_hi, 2);
            lrow[mt][0] = lrow[mt][0] * corr_lo + sum_lo;
            lrow[mt][1] = lrow[mt][1] * corr_hi + sum_hi;
#pragma unroll
            for (int nt = 0; nt < 8; nt++) {
                o[mt][nt][0] *= corr_lo; o[mt][nt][1] *= corr_lo;
                o[mt][nt][2] *= corr_hi; o[mt][nt][3] *= corr_hi;
            }
        }
        __syncwarp();

        // O += P @ V  (per warp: 32 x 64, k=32); P-frags via ldsm, V scalar
#pragma unroll
        for (int kk = 0; kk < 4; kk++) {
            uint32_t aa[2][4];
            ldsm_x4(aa[0], ps_b + (uint32_t)(pAoff + kk * 8) * 4);
            ldsm_x4(aa[1], ps_b + (uint32_t)(pAoff + 16 * KST + kk * 8) * 4);
#pragma unroll
            for (int nt = 0; nt < 8; nt++) {
                uint32_t bb[2];
                bb[0] = __float_as_uint(Vsb[(kk * 8 + c0)     * VST + nt * 8 + r0]);
                bb[1] = __float_as_uint(Vsb[(kk * 8 + c0 + 4) * VST + nt * 8 + r0]);
                mma_tf32(o[0][nt], aa[0], bb);
                mma_tf32(o[1][nt], aa[1], bb);
            }
        }
        __syncthreads();
    }

#pragma unroll
    for (int mt = 0; mt < 2; mt++) {
        const float inv_lo = 1.f / lrow[mt][0], inv_hi = 1.f / lrow[mt][1];
        const int qlo = q0 + w * 32 + mt * 16 + r0;
        float* Zlo = g_Z + ((size_t)b * SS + qlo) * DIM + h * HD;
        float* Zhi = Zlo + (size_t)8 * DIM;
#pragma unroll
        for (int nt = 0; nt < 8; nt++) {
            const int d = nt * 8 + 2 * c0;
            *(float2*)(Zlo + d) = make_float2(rna_tf32(o[mt][nt][0] * inv_lo),
                                              rna_tf32(o[mt][nt][1] * inv_lo));
            *(float2*)(Zhi + d) = make_float2(rna_tf32(o[mt][nt][2] * inv_hi),
                                              rna_tf32(o[mt][nt][3] * inv_hi));
        }
    }
}

// ---------------------------------------------------------------------------
extern "C" void kernel_launch(void* const* d_in, const int* in_sizes, int n_in,
                              void* d_out, int out_size)
{
    const float* q    = (const float*)d_in[0];
    const float* k    = (const float*)d_in[1];
    const float* v    = (const float*)d_in[2];
    const float* mask = (const float*)d_in[3];
    const float* Wq   = (const float*)d_in[4];
    const float* Wk   = (const float*)d_in[5];
    const float* Wv   = (const float*)d_in[6];
    const float* Wd   = (const float*)d_in[7];

    cudaFuncSetAttribute(qkv_gemm, cudaFuncAttributeMaxDynamicSharedMemorySize, GEMM_SMEM);
    cudaFuncSetAttribute(out_gemm, cudaFuncAttributeMaxDynamicSharedMemorySize, GEMM_SMEM);
    cudaFuncSetAttribute(attn_mma, cudaFuncAttributeMaxDynamicSharedMemorySize, ATTN_SMEM);

    // launch 1: pre-round everything + mask scan
    round_all<<<dim3(4096, 1, 8), 256>>>(q, k, v, Wq, Wk, Wv, Wd, mask);

    // launch 2: q/k/v projections
    qkv_gemm<<<dim3(MROWS/128, DIM/128, 3), 128, GEMM_SMEM>>>();

    // launch 3: flash attention
    attn_mma<<<dim3(SS/128, BB*NH), 128, ATTN_SMEM>>>(mask);

    // launch 4: output projection (+ maskflag reset)
    out_gemm<<<dim3(MROWS/128, DIM/128), 128, GEMM_SMEM>>>((float*)d_out);
}